// round 16
// baseline (speedup 1.0000x reference)
#include <cuda_runtime.h>
#include <cuda_fp16.h>
#include <cstdint>
#include <math.h>

#define GN   4096
#define FIN  512
#define FH   128
#define NH   4
#define FOUT 64
#define ALPHA 0.2f

// ---------------- scratch: EXACT same global set/sizes as the passing round --
__device__ __align__(16) float  g_h1[NH * GN * FH];   // fp32 H1; later aliased as fp16 x2h
__device__ float  g_h2[GN * FOUT];
__device__ __half g_h1h[NH * GN * FH];                // fp16 H1 (attn B operand)
__device__ __half g_h2h[GN * FOUT];
__device__ float  g_src1[NH * GN];
__device__ float  g_dst1[NH * GN];
__device__ float  g_src2[GN];
__device__ float  g_dst2[GN];
__device__ float  g_mdst[NH + 1];                     // ordered-uint encoded via casts
__device__ unsigned g_adj[GN * GN / 32];              // bit mask, 2 MB
__device__ __align__(16) float  g_x2[GN * (NH * FH)]; // aliased: feath|W1h|W2h, then attn2 partials

// half-aliased views (offsets in halfs; all 16B aligned)
#define FEATH ((__half*)g_x2)                          // 2,097,152 halfs
#define W1H   (((__half*)g_x2) + 2097152)              // 262,144 halfs
#define W2H   (((__half*)g_x2) + 2359296)              // 32,768 halfs
#define X2H   ((__half*)g_h1)                          // 2,097,152 halfs
// attn2 partial buffers (g_x2 is dead by attn2 time)
#define PNUM  ((float*)g_x2)                           // [4][GN][FOUT] = 4 MB
#define PDEN  (((float*)g_x2) + 1048576)               // [4][GN]

// ---------------- PTX helpers ------------------------------------------------
__device__ __forceinline__ unsigned s2u(const void* p) {
    unsigned a;
    asm("{ .reg .u64 t; cvta.to.shared.u64 t, %1; cvt.u32.u64 %0, t; }"
        : "=r"(a) : "l"(p));
    return a;
}

__device__ __forceinline__ void ldsm4(unsigned* d, unsigned addr) {
    asm volatile("ldmatrix.sync.aligned.m8n8.x4.shared.b16 {%0,%1,%2,%3}, [%4];"
                 : "=r"(d[0]), "=r"(d[1]), "=r"(d[2]), "=r"(d[3]) : "r"(addr));
}

__device__ __forceinline__ void ldsm4t(unsigned* d, unsigned addr) {
    asm volatile("ldmatrix.sync.aligned.m8n8.x4.trans.shared.b16 {%0,%1,%2,%3}, [%4];"
                 : "=r"(d[0]), "=r"(d[1]), "=r"(d[2]), "=r"(d[3]) : "r"(addr));
}

__device__ __forceinline__ void mma16816(float* c, const unsigned* a,
                                         unsigned b0, unsigned b1) {
    asm volatile(
        "mma.sync.aligned.m16n8k16.row.col.f32.f16.f16.f32 "
        "{%0,%1,%2,%3}, {%4,%5,%6,%7}, {%8,%9}, {%0,%1,%2,%3};"
        : "+f"(c[0]), "+f"(c[1]), "+f"(c[2]), "+f"(c[3])
        : "r"(a[0]), "r"(a[1]), "r"(a[2]), "r"(a[3]), "r"(b0), "r"(b1));
}

#define CP_ASYNC16(s, g) \
    asm volatile("cp.async.cg.shared.global [%0], [%1], 16;" :: "r"(s), "l"(g))
#define CP_COMMIT() asm volatile("cp.async.commit_group;")
#define CP_WAIT(n)  asm volatile("cp.async.wait_group %0;" :: "n"(n))

// monotone float<->uint map for atomicMax on signed floats
__device__ __forceinline__ unsigned f2ord(float f) {
    unsigned u = __float_as_uint(f);
    return (u & 0x80000000u) ? ~u : (u | 0x80000000u);
}
__device__ __forceinline__ float ord2f(unsigned u) {
    return (u & 0x80000000u) ? __uint_as_float(u & 0x7fffffffu)
                             : __uint_as_float(~u);
}

// ---------------- pack: adjacency bits + fp16 conversions + mdst init -------
__global__ void pack_adj_kernel(const int* __restrict__ adj,
                                const float* __restrict__ features,
                                const float* __restrict__ W1,
                                const float* __restrict__ W2) {
    int bid = blockIdx.x, tid = threadIdx.x;
    int i = bid * 256 + tid;
    unsigned bal = __ballot_sync(0xffffffffu, adj[i] > 0);
    if ((tid & 31) == 0) g_adj[i >> 5] = bal;

    if (bid == 0 && tid <= NH) ((unsigned*)g_mdst)[tid] = 0u;  // ordered -inf
    if (bid < 8192) {
        FEATH[i] = __float2half(features[i]);
    } else if (bid < 8192 + 1024) {
        int k = (bid - 8192) * 256 + tid;
        W1H[k] = __float2half(W1[k]);
    } else if (bid < 8192 + 1024 + 128) {
        int k = (bid - 9216) * 256 + tid;
        W2H[k] = __float2half(W2[k]);
    }
}

// ---------------- HMMA GEMM (cp.async double-buffered) ----------------------
template<int K, int NC, int LAYER>
__global__ __launch_bounds__(256) void hgemm_kernel() {
    constexpr int BK = 64, NKT = K / BK;
    constexpr int ASTR = BK + 8;
    constexpr int BSTR = NC + 8;
    constexpr int ABY = 128 * ASTR * 2;
    constexpr int BBY = BK * BSTR * 2;
    constexpr int N16 = NC / 32;

    extern __shared__ __align__(16) char smem_c[];
    const unsigned sbase = s2u(smem_c);
    const unsigned a32_0 = sbase,           a32_1 = sbase + ABY;
    const unsigned b32_0 = sbase + 2 * ABY, b32_1 = sbase + 2 * ABY + BBY;

    const int tid = threadIdx.x;
    const int r0 = blockIdx.x * 128;
    const __half* A  = (LAYER == 1) ? FEATH : X2H;
    const __half* Bm = ((LAYER == 1) ? W1H : W2H) + (size_t)blockIdx.z * K * NC;
    float*  C  = (LAYER == 1) ? (g_h1  + (size_t)blockIdx.z * GN * NC) : g_h2;
    __half* Ch = (LAYER == 1) ? (g_h1h + (size_t)blockIdx.z * GN * NC) : g_h2h;

    const int w = tid >> 5, lane = tid & 31;
    const int wm = (w & 3) * 32;
    const int wn = (w >> 2) * (NC / 2);

    float acc[2][2 * N16][4];
    #pragma unroll
    for (int a = 0; a < 2; a++)
        #pragma unroll
        for (int b = 0; b < 2 * N16; b++)
            #pragma unroll
            for (int c = 0; c < 4; c++) acc[a][b][c] = 0.f;

#define HG_STAGE(kt, adst, bdst)                                              \
    do {                                                                      \
        _Pragma("unroll")                                                     \
        for (int q = 0; q < 4; q++) {                                         \
            int c_ = tid + q * 256;                                           \
            int row_ = c_ >> 3, ch_ = c_ & 7;                                 \
            CP_ASYNC16((adst) + row_ * (ASTR * 2) + ch_ * 16,                 \
                       A + (size_t)(r0 + row_) * K + (kt) * BK + ch_ * 8);    \
        }                                                                     \
        _Pragma("unroll")                                                     \
        for (int q = 0; q < NC / 32; q++) {                                   \
            int c_ = tid + q * 256;                                           \
            int row_ = c_ / (NC / 8), ch_ = c_ % (NC / 8);                    \
            CP_ASYNC16((bdst) + row_ * (BSTR * 2) + ch_ * 16,                 \
                       Bm + (size_t)((kt) * BK + row_) * NC + ch_ * 8);       \
        }                                                                     \
    } while (0)

    HG_STAGE(0, a32_0, b32_0);
    CP_COMMIT();
    CP_WAIT(0);
    __syncthreads();

    for (int kt = 0; kt < NKT; kt++) {
        const int cur = kt & 1;
        const unsigned acur = cur ? a32_1 : a32_0;
        const unsigned bcur = cur ? b32_1 : b32_0;
        if (kt + 1 < NKT) {
            HG_STAGE(kt + 1, cur ? a32_0 : a32_1, cur ? b32_0 : b32_1);
            CP_COMMIT();
        }
        #pragma unroll
        for (int k16 = 0; k16 < BK / 16; k16++) {
            unsigned afr[2][4];
            #pragma unroll
            for (int mi = 0; mi < 2; mi++)
                ldsm4(afr[mi], acur +
                      ((wm + mi * 16 + (lane & 15)) * ASTR +
                       k16 * 16 + (lane >> 4) * 8) * 2);
            #pragma unroll
            for (int nj = 0; nj < N16; nj++) {
                unsigned bfr[4];
                ldsm4t(bfr, bcur +
                       ((k16 * 16 + (lane & 15)) * BSTR +
                        wn + nj * 16 + (lane >> 4) * 8) * 2);
                #pragma unroll
                for (int mi = 0; mi < 2; mi++) {
                    mma16816(acc[mi][2 * nj],     afr[mi], bfr[0], bfr[1]);
                    mma16816(acc[mi][2 * nj + 1], afr[mi], bfr[2], bfr[3]);
                }
            }
        }
        CP_WAIT(0);
        __syncthreads();
    }
#undef HG_STAGE

    const int g = lane >> 2, tig = lane & 3;
    #pragma unroll
    for (int mi = 0; mi < 2; mi++) {
        int rr0 = r0 + wm + mi * 16 + g;
        #pragma unroll
        for (int f = 0; f < 2 * N16; f++) {
            int col = wn + f * 8 + tig * 2;
            size_t i0 = (size_t)rr0 * NC + col;
            size_t i1 = (size_t)(rr0 + 8) * NC + col;
            *(float2*)&C[i0] = make_float2(acc[mi][f][0], acc[mi][f][1]);
            *(float2*)&C[i1] = make_float2(acc[mi][f][2], acc[mi][f][3]);
            *(__half2*)&Ch[i0] = __floats2half2_rn(acc[mi][f][0], acc[mi][f][1]);
            *(__half2*)&Ch[i1] = __floats2half2_rn(acc[mi][f][2], acc[mi][f][3]);
        }
    }
}

// ---------------- src/dst projections (+ fused atomic max of dst) -----------
template<int F, int LAYER>
__global__ void srcdst_kernel(const float* __restrict__ a_src,
                              const float* __restrict__ a_dst) {
    const float* Hm = (LAYER == 1) ? g_h1 : g_h2;
    float* so  = (LAYER == 1) ? g_src1 : g_src2;
    float* dso = (LAYER == 1) ? g_dst1 : g_dst2;
    int gw   = (blockIdx.x * blockDim.x + threadIdx.x) >> 5;
    int lane = threadIdx.x & 31;
    int hh = gw / GN;
    const float* row = Hm + (size_t)gw * F;
    float s = 0.f, d = 0.f;
    for (int c = lane; c < F; c += 32) {
        float v = row[c];
        s += v * a_src[hh * F + c];
        d += v * a_dst[hh * F + c];
    }
    for (int o = 16; o; o >>= 1) {
        s += __shfl_xor_sync(0xffffffffu, s, o);
        d += __shfl_xor_sync(0xffffffffu, d, o);
    }
    if (lane == 0) {
        so[gw] = s; dso[gw] = d;
        atomicMax(((unsigned*)g_mdst) + ((LAYER == 1) ? hh : NH), f2ord(d));
    }
}

// ---------------- fused masked-softmax attention (HMMA, half2 register-P) ---
// Warp tile: MI=2 (32 rows) x WN=NB/4 cols -> 2x fewer redundant B loads.
// B fragments register double-buffered across k16 (ldsm ahead of mma chain).
// One __syncthreads per tile (cp.async double buffer). Denominators via
// ones-B MMAs on warps 0-1 (exact fp32 sums of the same fp16 p).
template<int BM, int NB, int LAYER, int JSPLIT>
__global__ __launch_bounds__(256, 2) void attn_mma_kernel(float* __restrict__ dout) {
    constexpr int KT  = 128;
    constexpr int NTS = (GN / KT) / JSPLIT;
    constexpr int WN  = NB / 4;            // 32 or 16
    constexpr int N16 = WN / 16;           // 2 or 1
    constexpr int HSTR = NB + 8;
    constexpr int HBY  = KT * HSTR * 2;
    constexpr unsigned ONES2 = 0x3C003C00u;

    extern __shared__ __align__(16) char smem_c[];
    float*    dpart_s = (float*)smem_c;                  // [64]
    float*    inv_s   = (float*)(smem_c + 256);          // [64]
    unsigned* lut_s   = (unsigned*)(smem_c + 512);       // [4]
    uint2*    edp0    = (uint2*)(smem_c + 640);          // [64] buf0
    uint2*    edp1    = (uint2*)(smem_c + 1152);         // [64] buf1
    unsigned* adj0    = (unsigned*)(smem_c + 1664);      // [256] buf0
    unsigned* adj1    = (unsigned*)(smem_c + 2688);      // [256] buf1
    const unsigned hb0 = s2u(smem_c) + 3712;
    const unsigned hb1 = hb0 + HBY;

    const int tid = threadIdx.x;
    const int h   = blockIdx.y;
    const int i0  = blockIdx.x * BM;
    const int js  = (JSPLIT > 1) ? blockIdx.z : 0;
    const int jt_end = (js + 1) * NTS;

    const float* srcv = (LAYER == 1) ? (g_src1 + (size_t)h * GN) : g_src2;
    const float* dstv = (LAYER == 1) ? (g_dst1 + (size_t)h * GN) : g_dst2;
    const __half* Hh  = (LAYER == 1) ? (g_h1h + (size_t)h * GN * FH) : g_h2h;
    const float md = ord2f(((unsigned*)g_mdst)[(LAYER == 1) ? h : NH]);

    if (tid < 4)
        lut_s[tid] = ((tid & 1) ? 0x0000FFFFu : 0u) | ((tid & 2) ? 0xFFFF0000u : 0u);

    const int w = tid >> 5, lane = tid & 31;
    const int g = lane >> 2, tig = lane & 3;
    const int wm = (w & 1) * 32;           // MI=2: rows wm..wm+31
    const int wn = (w >> 1) * WN;          // 4 col groups

    // per-row factors for 4 row positions (mi*16 + {0,8} + g), all <= 1
    __half2 esA[2][2], esB[2][2];
    #pragma unroll
    for (int mi = 0; mi < 2; mi++)
        #pragma unroll
        for (int hf = 0; hf < 2; hf++) {
            float s = srcv[i0 + wm + mi * 16 + hf * 8 + g];
            float t = s + md;
            float m = (t > 0.f) ? t : (ALPHA * t);
            esA[mi][hf] = __float2half2_rn(__expf(t - m));
            esB[mi][hf] = __float2half2_rn(__expf(0.2f * t - m));
        }

    float acc[2][2 * N16][4];
    #pragma unroll
    for (int a = 0; a < 2; a++)
        #pragma unroll
        for (int b = 0; b < 2 * N16; b++)
            #pragma unroll
            for (int c = 0; c < 4; c++) acc[a][b][c] = 0.f;
    float accd[2][4] = {{0.f, 0.f, 0.f, 0.f}, {0.f, 0.f, 0.f, 0.f}};

#define STG_H(jt, hdst)                                                       \
    do {                                                                      \
        _Pragma("unroll")                                                     \
        for (int q = 0; q < KT * NB / 8 / 256; q++) {                         \
            int c_ = tid + q * 256;                                           \
            int row_ = c_ / (NB / 8), ch_ = c_ % (NB / 8);                    \
            CP_ASYNC16((hdst) + row_ * (HSTR * 2) + ch_ * 16,                 \
                       Hh + (size_t)((jt) * KT + row_) * NB + ch_ * 8);       \
        }                                                                     \
    } while (0)

#define STG_EA(jt, ebuf, abuf)                                                \
    do {                                                                      \
        if (tid < KT / 2) {                                                   \
            float d0_ = __ldg(dstv + (jt) * KT + 2 * tid)     - md;           \
            float d1_ = __ldg(dstv + (jt) * KT + 2 * tid + 1) - md;           \
            __half2 ea_ = __floats2half2_rn(__expf(d0_), __expf(d1_));        \
            __half2 eb_ = __floats2half2_rn(__expf(0.2f * d0_),               \
                                            __expf(0.2f * d1_));              \
            uint2 e_;                                                         \
            e_.x = *(unsigned*)&ea_;                                          \
            e_.y = *(unsigned*)&eb_;                                          \
            (ebuf)[tid] = e_;                                                 \
        }                                                                     \
        {                                                                     \
            int rr_ = tid >> 2, ww_ = tid & 3;                                \
            (abuf)[tid] = __ldg(g_adj + (size_t)(i0 + rr_) * (GN / 32)        \
                                + (jt) * 4 + ww_);                            \
        }                                                                     \
    } while (0)

    STG_H(js * NTS, hb0);
    CP_COMMIT();
    STG_EA(js * NTS, edp0, adj0);
    CP_WAIT(0);
    __syncthreads();

    for (int jt = js * NTS; jt < jt_end; jt++) {
        const int cur = jt & 1;
        const unsigned hbc = cur ? hb1 : hb0;
        const uint2*    edpc = cur ? edp1 : edp0;
        const unsigned* adjc = cur ? adj1 : adj0;
        if (jt + 1 < jt_end) {
            STG_H(jt + 1, cur ? hb0 : hb1);
            CP_COMMIT();
            STG_EA(jt + 1, cur ? edp0 : edp1, cur ? adj0 : adj1);
        }

        unsigned bcur[N16 * 4], bnxt[N16 * 4];
        #pragma unroll
        for (int nj = 0; nj < N16; nj++)
            ldsm4t(bcur + nj * 4, hbc +
                   ((lane & 15) * HSTR + wn + nj * 16 + (lane >> 4) * 8) * 2);

        #pragma unroll
        for (int k16 = 0; k16 < KT / 16; k16++) {
            if (k16 + 1 < KT / 16) {
                #pragma unroll
                for (int nj = 0; nj < N16; nj++)
                    ldsm4t(bnxt + nj * 4, hbc +
                           (((k16 + 1) * 16 + (lane & 15)) * HSTR +
                            wn + nj * 16 + (lane >> 4) * 8) * 2);
            }
            const int kw = k16 >> 1;
            const int sh = (k16 & 1) * 16;
            uint2 elo = edpc[k16 * 8 + tig];
            uint2 ehi = edpc[k16 * 8 + 4 + tig];
            __half2 eAlo = *(__half2*)&elo.x, eBlo = *(__half2*)&elo.y;
            __half2 eAhi = *(__half2*)&ehi.x, eBhi = *(__half2*)&ehi.y;
            const int b0 = sh + tig * 2, b2 = sh + 8 + tig * 2;
            #pragma unroll
            for (int mi = 0; mi < 2; mi++) {
                unsigned aw0 = adjc[(wm + mi * 16 + g) * 4 + kw];
                unsigned aw1 = adjc[(wm + mi * 16 + 8 + g) * 4 + kw];
                __half2 p0lo = __hmax2(__hmul2(esA[mi][0], eAlo),
                                       __hmul2(esB[mi][0], eBlo));
                __half2 p1lo = __hmax2(__hmul2(esA[mi][1], eAlo),
                                       __hmul2(esB[mi][1], eBlo));
                __half2 p0hi = __hmax2(__hmul2(esA[mi][0], eAhi),
                                       __hmul2(esB[mi][0], eBhi));
                __half2 p1hi = __hmax2(__hmul2(esA[mi][1], eAhi),
                                       __hmul2(esB[mi][1], eBhi));
                unsigned afr[4];
                afr[0] = (*(unsigned*)&p0lo) & lut_s[(aw0 >> b0) & 3u];
                afr[1] = (*(unsigned*)&p1lo) & lut_s[(aw1 >> b0) & 3u];
                afr[2] = (*(unsigned*)&p0hi) & lut_s[(aw0 >> b2) & 3u];
                afr[3] = (*(unsigned*)&p1hi) & lut_s[(aw1 >> b2) & 3u];
                if (w < 2) mma16816(accd[mi], afr, ONES2, ONES2);  // denoms
                #pragma unroll
                for (int nj = 0; nj < N16; nj++) {
                    mma16816(acc[mi][2 * nj],     afr, bcur[nj * 4],     bcur[nj * 4 + 1]);
                    mma16816(acc[mi][2 * nj + 1], afr, bcur[nj * 4 + 2], bcur[nj * 4 + 3]);
                }
            }
            #pragma unroll
            for (int q = 0; q < N16 * 4; q++) bcur[q] = bnxt[q];
        }
        CP_WAIT(0);
        __syncthreads();                     // publish jt+1, retire buf cur
    }
#undef STG_H
#undef STG_EA

    // denominators: warps 0-1 cover rows wm..wm+31 (accd[mi][0], accd[mi][2])
    if (w < 2 && tig == 0) {
        #pragma unroll
        for (int mi = 0; mi < 2; mi++) {
            dpart_s[wm + mi * 16 + g]     = accd[mi][0];
            dpart_s[wm + mi * 16 + 8 + g] = accd[mi][2];
        }
    }
    __syncthreads();
    if (tid < BM) {
        if (LAYER == 1) inv_s[tid] = 1.f / dpart_s[tid];
        else            PDEN[js * GN + i0 + tid] = dpart_s[tid];
    }
    __syncthreads();

    #pragma unroll
    for (int mi = 0; mi < 2; mi++) {
        int rr0 = wm + mi * 16 + g;
        if (LAYER == 1) {
            float inv0 = inv_s[rr0], inv1 = inv_s[rr0 + 8];
            #pragma unroll
            for (int f = 0; f < 2 * N16; f++) {
                int col = wn + f * 8 + tig * 2;
                float v0 = acc[mi][f][0] * inv0;
                float v1 = acc[mi][f][1] * inv0;
                float v2 = acc[mi][f][2] * inv1;
                float v3 = acc[mi][f][3] * inv1;
                v0 = (v0 > 0.f) ? v0 : expm1f(v0);
                v1 = (v1 > 0.f) ? v1 : expm1f(v1);
                v2 = (v2 > 0.f) ? v2 : expm1f(v2);
                v3 = (v3 > 0.f) ? v3 : expm1f(v3);
                size_t o0 = (size_t)(i0 + rr0) * (NH * FH) + h * FH + col;
                size_t o1 = (size_t)(i0 + rr0 + 8) * (NH * FH) + h * FH + col;
                *(__half2*)&X2H[o0] = __floats2half2_rn(v0, v1);
                *(__half2*)&X2H[o1] = __floats2half2_rn(v2, v3);
            }
        } else {
            #pragma unroll
            for (int f = 0; f < 2 * N16; f++) {
                int col = wn + f * 8 + tig * 2;
                float* o0 = PNUM + (size_t)js * GN * FOUT + (size_t)(i0 + rr0) * FOUT + col;
                float* o1 = PNUM + (size_t)js * GN * FOUT + (size_t)(i0 + rr0 + 8) * FOUT + col;
                *(float2*)o0 = make_float2(acc[mi][f][0], acc[mi][f][1]);
                *(float2*)o1 = make_float2(acc[mi][f][2], acc[mi][f][3]);
            }
        }
    }
}

// ---------------- combine: sum partials, normalize, ELU, log_softmax --------
__global__ void combine_kernel(float* __restrict__ out) {
    int gw   = (blockIdx.x * blockDim.x + threadIdx.x) >> 5;   // row
    int lane = threadIdx.x & 31;
    float den = 0.f;
    #pragma unroll
    for (int js = 0; js < 4; js++) den += PDEN[js * GN + gw];
    float inv = 1.f / den;
    float v0 = 0.f, v1 = 0.f;
    #pragma unroll
    for (int js = 0; js < 4; js++) {
        const float* p = PNUM + (size_t)js * GN * FOUT + (size_t)gw * FOUT;
        v0 += p[lane];
        v1 += p[lane + 32];
    }
    v0 *= inv; v1 *= inv;
    v0 = (v0 > 0.f) ? v0 : expm1f(v0);
    v1 = (v1 > 0.f) ? v1 : expm1f(v1);
    float m = fmaxf(v0, v1);
    #pragma unroll
    for (int o = 16; o; o >>= 1) m = fmaxf(m, __shfl_xor_sync(0xffffffffu, m, o));
    float s = __expf(v0 - m) + __expf(v1 - m);
    #pragma unroll
    for (int o = 16; o; o >>= 1) s += __shfl_xor_sync(0xffffffffu, s, o);
    float lse = m + logf(s);
    out[(size_t)gw * FOUT + lane]      = v0 - lse;
    out[(size_t)gw * FOUT + lane + 32] = v1 - lse;
}

// ---------------- launch ----------------------------------------------------
extern "C" void kernel_launch(void* const* d_in, const int* in_sizes, int n_in,
                              void* d_out, int out_size) {
    const float* features = (const float*)d_in[0];
    const int*   adj      = (const int*)d_in[1];
    const float* W1  = (const float*)d_in[2];
    const float* a1s = (const float*)d_in[3];
    const float* a1d = (const float*)d_in[4];
    const float* W2  = (const float*)d_in[5];
    const float* a2s = (const float*)d_in[6];
    const float* a2d = (const float*)d_in[7];
    float* out = (float*)d_out;

    const int SM_G1 = 2 * 128 * 72 * 2 + 2 * 64 * 136 * 2;   // 71680
    const int SM_G2 = 2 * 128 * 72 * 2 + 2 * 64 * 72 * 2;    // 55296
    const int SMEM1 = 3712 + 2 * 128 * 136 * 2;              // 73344
    const int SMEM2 = 3712 + 2 * 128 * 72 * 2;               // 40576
    cudaFuncSetAttribute(hgemm_kernel<FIN, FH, 1>,
                         cudaFuncAttributeMaxDynamicSharedMemorySize, SM_G1);
    cudaFuncSetAttribute(hgemm_kernel<NH * FH, FOUT, 2>,
                         cudaFuncAttributeMaxDynamicSharedMemorySize, SM_G2);
    cudaFuncSetAttribute(attn_mma_kernel<64, FH, 1, 1>,
                         cudaFuncAttributeMaxDynamicSharedMemorySize, SMEM1);
    cudaFuncSetAttribute(attn_mma_kernel<64, FOUT, 2, 4>,
                         cudaFuncAttributeMaxDynamicSharedMemorySize, SMEM2);

    pack_adj_kernel<<<(GN * GN) / 256, 256>>>(adj, features, W1, W2);

    // layer 1
    hgemm_kernel<FIN, FH, 1><<<dim3(GN / 128, 1, NH), 256, SM_G1>>>();
    srcdst_kernel<FH, 1><<<(NH * GN) / 8, 256>>>(a1s, a1d);
    attn_mma_kernel<64, FH, 1, 1><<<dim3(GN / 64, NH, 1), 256, SMEM1>>>(nullptr);

    // layer 2
    hgemm_kernel<NH * FH, FOUT, 2><<<dim3(GN / 128, 1, 1), 256, SM_G2>>>();
    srcdst_kernel<FOUT, 2><<<GN / 8, 256>>>(a2s, a2d);
    attn_mma_kernel<64, FOUT, 2, 4><<<dim3(GN / 64, 1, 4), 256, SMEM2>>>(nullptr);
    combine_kernel<<<GN / 8, 256>>>(out);
}

// round 17
// speedup vs baseline: 1.0728x; 1.0728x over previous
#include <cuda_runtime.h>
#include <cuda_fp16.h>
#include <cstdint>
#include <math.h>

#define GN   4096
#define FIN  512
#define FH   128
#define NH   4
#define FOUT 64
#define ALPHA 0.2f

// ---------------- scratch: EXACT same global set/sizes as the passing round --
__device__ __align__(16) float  g_h1[NH * GN * FH];   // fp32 H1; later aliased as fp16 x2h
__device__ float  g_h2[GN * FOUT];
__device__ __half g_h1h[NH * GN * FH];                // fp16 H1 (attn B operand)
__device__ __half g_h2h[GN * FOUT];
__device__ float  g_src1[NH * GN];
__device__ float  g_dst1[NH * GN];
__device__ float  g_src2[GN];
__device__ float  g_dst2[GN];
__device__ float  g_mdst[NH + 1];                     // ordered-uint encoded via casts
__device__ unsigned g_adj[GN * GN / 32];              // bit mask, 2 MB
__device__ __align__(16) float  g_x2[GN * (NH * FH)]; // aliased: feath|W1h|W2h, then attn2 partials

// half-aliased views (offsets in halfs; all 16B aligned)
#define FEATH ((__half*)g_x2)                          // 2,097,152 halfs
#define W1H   (((__half*)g_x2) + 2097152)              // 262,144 halfs
#define W2H   (((__half*)g_x2) + 2359296)              // 32,768 halfs
#define X2H   ((__half*)g_h1)                          // 2,097,152 halfs
// attn2 partial buffers (g_x2 is dead by attn2 time)
#define PNUM  ((float*)g_x2)                           // [4][GN][FOUT] = 4 MB
#define PDEN  (((float*)g_x2) + 1048576)               // [4][GN]

// ---------------- PTX helpers ------------------------------------------------
__device__ __forceinline__ unsigned s2u(const void* p) {
    unsigned a;
    asm("{ .reg .u64 t; cvta.to.shared.u64 t, %1; cvt.u32.u64 %0, t; }"
        : "=r"(a) : "l"(p));
    return a;
}

__device__ __forceinline__ void ldsm4(unsigned* d, unsigned addr) {
    asm volatile("ldmatrix.sync.aligned.m8n8.x4.shared.b16 {%0,%1,%2,%3}, [%4];"
                 : "=r"(d[0]), "=r"(d[1]), "=r"(d[2]), "=r"(d[3]) : "r"(addr));
}

__device__ __forceinline__ void ldsm4t(unsigned* d, unsigned addr) {
    asm volatile("ldmatrix.sync.aligned.m8n8.x4.trans.shared.b16 {%0,%1,%2,%3}, [%4];"
                 : "=r"(d[0]), "=r"(d[1]), "=r"(d[2]), "=r"(d[3]) : "r"(addr));
}

__device__ __forceinline__ void mma16816(float* c, const unsigned* a,
                                         unsigned b0, unsigned b1) {
    asm volatile(
        "mma.sync.aligned.m16n8k16.row.col.f32.f16.f16.f32 "
        "{%0,%1,%2,%3}, {%4,%5,%6,%7}, {%8,%9}, {%0,%1,%2,%3};"
        : "+f"(c[0]), "+f"(c[1]), "+f"(c[2]), "+f"(c[3])
        : "r"(a[0]), "r"(a[1]), "r"(a[2]), "r"(a[3]), "r"(b0), "r"(b1));
}

#define CP_ASYNC16(s, g) \
    asm volatile("cp.async.cg.shared.global [%0], [%1], 16;" :: "r"(s), "l"(g))
#define CP_COMMIT() asm volatile("cp.async.commit_group;")
#define CP_WAIT(n)  asm volatile("cp.async.wait_group %0;" :: "n"(n))

// monotone float<->uint map for atomicMax on signed floats
__device__ __forceinline__ unsigned f2ord(float f) {
    unsigned u = __float_as_uint(f);
    return (u & 0x80000000u) ? ~u : (u | 0x80000000u);
}
__device__ __forceinline__ float ord2f(unsigned u) {
    return (u & 0x80000000u) ? __uint_as_float(u & 0x7fffffffu)
                             : __uint_as_float(~u);
}

// ---------------- pack: adjacency bits + fp16 conversions + mdst init -------
__global__ void pack_adj_kernel(const int* __restrict__ adj,
                                const float* __restrict__ features,
                                const float* __restrict__ W1,
                                const float* __restrict__ W2) {
    int bid = blockIdx.x, tid = threadIdx.x;
    int i = bid * 256 + tid;
    unsigned bal = __ballot_sync(0xffffffffu, adj[i] > 0);
    if ((tid & 31) == 0) g_adj[i >> 5] = bal;

    if (bid == 0 && tid <= NH) ((unsigned*)g_mdst)[tid] = 0u;  // ordered -inf
    if (bid < 8192) {
        FEATH[i] = __float2half(features[i]);
    } else if (bid < 8192 + 1024) {
        int k = (bid - 8192) * 256 + tid;
        W1H[k] = __float2half(W1[k]);
    } else if (bid < 8192 + 1024 + 128) {
        int k = (bid - 9216) * 256 + tid;
        W2H[k] = __float2half(W2[k]);
    }
}

// ---------------- HMMA GEMM (cp.async double-buffered) ----------------------
template<int K, int NC, int LAYER>
__global__ __launch_bounds__(256) void hgemm_kernel() {
    constexpr int BK = 64, NKT = K / BK;
    constexpr int ASTR = BK + 8;
    constexpr int BSTR = NC + 8;
    constexpr int ABY = 128 * ASTR * 2;
    constexpr int BBY = BK * BSTR * 2;
    constexpr int N16 = NC / 32;

    extern __shared__ __align__(16) char smem_c[];
    const unsigned sbase = s2u(smem_c);
    const unsigned a32_0 = sbase,           a32_1 = sbase + ABY;
    const unsigned b32_0 = sbase + 2 * ABY, b32_1 = sbase + 2 * ABY + BBY;

    const int tid = threadIdx.x;
    const int r0 = blockIdx.x * 128;
    const __half* A  = (LAYER == 1) ? FEATH : X2H;
    const __half* Bm = ((LAYER == 1) ? W1H : W2H) + (size_t)blockIdx.z * K * NC;
    float*  C  = (LAYER == 1) ? (g_h1  + (size_t)blockIdx.z * GN * NC) : g_h2;
    __half* Ch = (LAYER == 1) ? (g_h1h + (size_t)blockIdx.z * GN * NC) : g_h2h;

    const int w = tid >> 5, lane = tid & 31;
    const int wm = (w & 3) * 32;
    const int wn = (w >> 2) * (NC / 2);

    float acc[2][2 * N16][4];
    #pragma unroll
    for (int a = 0; a < 2; a++)
        #pragma unroll
        for (int b = 0; b < 2 * N16; b++)
            #pragma unroll
            for (int c = 0; c < 4; c++) acc[a][b][c] = 0.f;

#define HG_STAGE(kt, adst, bdst)                                              \
    do {                                                                      \
        _Pragma("unroll")                                                     \
        for (int q = 0; q < 4; q++) {                                         \
            int c_ = tid + q * 256;                                           \
            int row_ = c_ >> 3, ch_ = c_ & 7;                                 \
            CP_ASYNC16((adst) + row_ * (ASTR * 2) + ch_ * 16,                 \
                       A + (size_t)(r0 + row_) * K + (kt) * BK + ch_ * 8);    \
        }                                                                     \
        _Pragma("unroll")                                                     \
        for (int q = 0; q < NC / 32; q++) {                                   \
            int c_ = tid + q * 256;                                           \
            int row_ = c_ / (NC / 8), ch_ = c_ % (NC / 8);                    \
            CP_ASYNC16((bdst) + row_ * (BSTR * 2) + ch_ * 16,                 \
                       Bm + (size_t)((kt) * BK + row_) * NC + ch_ * 8);       \
        }                                                                     \
    } while (0)

    HG_STAGE(0, a32_0, b32_0);
    CP_COMMIT();
    CP_WAIT(0);
    __syncthreads();

    for (int kt = 0; kt < NKT; kt++) {
        const int cur = kt & 1;
        const unsigned acur = cur ? a32_1 : a32_0;
        const unsigned bcur = cur ? b32_1 : b32_0;
        if (kt + 1 < NKT) {
            HG_STAGE(kt + 1, cur ? a32_0 : a32_1, cur ? b32_0 : b32_1);
            CP_COMMIT();
        }
        #pragma unroll
        for (int k16 = 0; k16 < BK / 16; k16++) {
            unsigned afr[2][4];
            #pragma unroll
            for (int mi = 0; mi < 2; mi++)
                ldsm4(afr[mi], acur +
                      ((wm + mi * 16 + (lane & 15)) * ASTR +
                       k16 * 16 + (lane >> 4) * 8) * 2);
            #pragma unroll
            for (int nj = 0; nj < N16; nj++) {
                unsigned bfr[4];
                ldsm4t(bfr, bcur +
                       ((k16 * 16 + (lane & 15)) * BSTR +
                        wn + nj * 16 + (lane >> 4) * 8) * 2);
                #pragma unroll
                for (int mi = 0; mi < 2; mi++) {
                    mma16816(acc[mi][2 * nj],     afr[mi], bfr[0], bfr[1]);
                    mma16816(acc[mi][2 * nj + 1], afr[mi], bfr[2], bfr[3]);
                }
            }
        }
        CP_WAIT(0);
        __syncthreads();
    }
#undef HG_STAGE

    const int g = lane >> 2, tig = lane & 3;
    #pragma unroll
    for (int mi = 0; mi < 2; mi++) {
        int rr0 = r0 + wm + mi * 16 + g;
        #pragma unroll
        for (int f = 0; f < 2 * N16; f++) {
            int col = wn + f * 8 + tig * 2;
            size_t i0 = (size_t)rr0 * NC + col;
            size_t i1 = (size_t)(rr0 + 8) * NC + col;
            *(float2*)&C[i0] = make_float2(acc[mi][f][0], acc[mi][f][1]);
            *(float2*)&C[i1] = make_float2(acc[mi][f][2], acc[mi][f][3]);
            *(__half2*)&Ch[i0] = __floats2half2_rn(acc[mi][f][0], acc[mi][f][1]);
            *(__half2*)&Ch[i1] = __floats2half2_rn(acc[mi][f][2], acc[mi][f][3]);
        }
    }
}

// ---------------- src/dst projections (+ fused atomic max of dst) -----------
template<int F, int LAYER>
__global__ void srcdst_kernel(const float* __restrict__ a_src,
                              const float* __restrict__ a_dst) {
    const float* Hm = (LAYER == 1) ? g_h1 : g_h2;
    float* so  = (LAYER == 1) ? g_src1 : g_src2;
    float* dso = (LAYER == 1) ? g_dst1 : g_dst2;
    int gw   = (blockIdx.x * blockDim.x + threadIdx.x) >> 5;
    int lane = threadIdx.x & 31;
    int hh = gw / GN;
    const float* row = Hm + (size_t)gw * F;
    float s = 0.f, d = 0.f;
    for (int c = lane; c < F; c += 32) {
        float v = row[c];
        s += v * a_src[hh * F + c];
        d += v * a_dst[hh * F + c];
    }
    for (int o = 16; o; o >>= 1) {
        s += __shfl_xor_sync(0xffffffffu, s, o);
        d += __shfl_xor_sync(0xffffffffu, d, o);
    }
    if (lane == 0) {
        so[gw] = s; dso[gw] = d;
        atomicMax(((unsigned*)g_mdst) + ((LAYER == 1) ? hh : NH), f2ord(d));
    }
}

// ---------------- fused masked-softmax attention (HMMA, half2 register-P) ---
// Round-15 configuration (best measured): 4x2 warp layout, double-buffered
// cp.async pipeline for H + {exp pairs, adjacency}, two syncs per tile.
// p = adj * max(esA_i*edA_j, esB_i*edB_j); denominators via ones-B MMA.
template<int BM, int NB, int LAYER, int JSPLIT>
__global__ __launch_bounds__(256, 2) void attn_mma_kernel(float* __restrict__ dout) {
    constexpr int KT  = 128;
    constexpr int NTS = (GN / KT) / JSPLIT;
    constexpr int WM  = BM / 4;            // 16
    constexpr int WN  = NB / 2;            // 64 or 32
    constexpr int N16 = WN / 16;           // 4 or 2
    constexpr int HSTR = NB + 8;
    constexpr int HBY  = KT * HSTR * 2;
    constexpr unsigned ONES2 = 0x3C003C00u;

    extern __shared__ __align__(16) char smem_c[];
    float*    dpart_s = (float*)smem_c;                  // [64]
    float*    inv_s   = (float*)(smem_c + 256);          // [64]
    unsigned* lut_s   = (unsigned*)(smem_c + 512);       // [4]
    uint2*    edp0    = (uint2*)(smem_c + 640);          // [64] buf0
    uint2*    edp1    = (uint2*)(smem_c + 1152);         // [64] buf1
    unsigned* adj0    = (unsigned*)(smem_c + 1664);      // [256] buf0
    unsigned* adj1    = (unsigned*)(smem_c + 2688);      // [256] buf1
    const unsigned hb0 = s2u(smem_c) + 3712;
    const unsigned hb1 = hb0 + HBY;

    const int tid = threadIdx.x;
    const int h   = blockIdx.y;
    const int i0  = blockIdx.x * BM;
    const int js  = (JSPLIT > 1) ? blockIdx.z : 0;
    const int jt_end = (js + 1) * NTS;

    const float* srcv = (LAYER == 1) ? (g_src1 + (size_t)h * GN) : g_src2;
    const float* dstv = (LAYER == 1) ? (g_dst1 + (size_t)h * GN) : g_dst2;
    const __half* Hh  = (LAYER == 1) ? (g_h1h + (size_t)h * GN * FH) : g_h2h;
    const float md = ord2f(((unsigned*)g_mdst)[(LAYER == 1) ? h : NH]);

    if (tid < 4)
        lut_s[tid] = ((tid & 1) ? 0x0000FFFFu : 0u) | ((tid & 2) ? 0xFFFF0000u : 0u);

    const int w = tid >> 5, lane = tid & 31;
    const int g = lane >> 2, tig = lane & 3;
    const int wm = (w & 3) * WM;
    const int wn = (w >> 2) * WN;

    // per-row factors (rows wm+g and wm+g+8), all <= 1
    const float s0 = srcv[i0 + wm + g];
    const float s1 = srcv[i0 + wm + g + 8];
    float t0 = s0 + md; float m0 = (t0 > 0.f) ? t0 : (ALPHA * t0);
    float t1 = s1 + md; float m1 = (t1 > 0.f) ? t1 : (ALPHA * t1);
    const __half2 esA0 = __float2half2_rn(__expf(t0 - m0));
    const __half2 esB0 = __float2half2_rn(__expf(0.2f * t0 - m0));
    const __half2 esA1 = __float2half2_rn(__expf(t1 - m1));
    const __half2 esB1 = __float2half2_rn(__expf(0.2f * t1 - m1));

    float acc[2 * N16][4];
    #pragma unroll
    for (int b = 0; b < 2 * N16; b++)
        #pragma unroll
        for (int c = 0; c < 4; c++) acc[b][c] = 0.f;
    float accd[4] = {0.f, 0.f, 0.f, 0.f};

#define STG_H(jt, hdst)                                                       \
    do {                                                                      \
        _Pragma("unroll")                                                     \
        for (int q = 0; q < KT * NB / 8 / 256; q++) {                         \
            int c_ = tid + q * 256;                                           \
            int row_ = c_ / (NB / 8), ch_ = c_ % (NB / 8);                    \
            CP_ASYNC16((hdst) + row_ * (HSTR * 2) + ch_ * 16,                 \
                       Hh + (size_t)((jt) * KT + row_) * NB + ch_ * 8);       \
        }                                                                     \
    } while (0)

#define STG_EA(jt, ebuf, abuf)                                                \
    do {                                                                      \
        if (tid < KT / 2) {                                                   \
            float d0_ = __ldg(dstv + (jt) * KT + 2 * tid)     - md;           \
            float d1_ = __ldg(dstv + (jt) * KT + 2 * tid + 1) - md;           \
            __half2 ea_ = __floats2half2_rn(__expf(d0_), __expf(d1_));        \
            __half2 eb_ = __floats2half2_rn(__expf(0.2f * d0_),               \
                                            __expf(0.2f * d1_));              \
            uint2 e_;                                                         \
            e_.x = *(unsigned*)&ea_;                                          \
            e_.y = *(unsigned*)&eb_;                                          \
            (ebuf)[tid] = e_;                                                 \
        }                                                                     \
        {                                                                     \
            int rr_ = tid >> 2, ww_ = tid & 3;                                \
            (abuf)[tid] = __ldg(g_adj + (size_t)(i0 + rr_) * (GN / 32)        \
                                + (jt) * 4 + ww_);                            \
        }                                                                     \
    } while (0)

    STG_H(js * NTS, hb0);
    CP_COMMIT();
    STG_EA(js * NTS, edp0, adj0);

    for (int jt = js * NTS; jt < jt_end; jt++) {
        const int cur = jt & 1;
        const unsigned hbc = cur ? hb1 : hb0;
        if (jt + 1 < jt_end) {
            STG_H(jt + 1, cur ? hb0 : hb1);
            CP_COMMIT();
            STG_EA(jt + 1, cur ? edp0 : edp1, cur ? adj0 : adj1);
            CP_WAIT(1);
        } else {
            CP_WAIT(0);
        }
        __syncthreads();                     // tile jt fully staged, visible
        const uint2*    edpc = cur ? edp1 : edp0;
        const unsigned* adjc = cur ? adj1 : adj0;

        #pragma unroll
        for (int k16 = 0; k16 < KT / 16; k16++) {
            const int kw = k16 >> 1;
            const int sh = (k16 & 1) * 16;
            unsigned aw0 = adjc[(wm + g) * 4 + kw];
            unsigned aw1 = adjc[(wm + g + 8) * 4 + kw];
            uint2 elo = edpc[k16 * 8 + tig];
            uint2 ehi = edpc[k16 * 8 + 4 + tig];
            __half2 eAlo = *(__half2*)&elo.x, eBlo = *(__half2*)&elo.y;
            __half2 eAhi = *(__half2*)&ehi.x, eBhi = *(__half2*)&ehi.y;
            const int b0 = sh + tig * 2, b2 = sh + 8 + tig * 2;
            __half2 p0lo = __hmax2(__hmul2(esA0, eAlo), __hmul2(esB0, eBlo));
            __half2 p1lo = __hmax2(__hmul2(esA1, eAlo), __hmul2(esB1, eBlo));
            __half2 p0hi = __hmax2(__hmul2(esA0, eAhi), __hmul2(esB0, eBhi));
            __half2 p1hi = __hmax2(__hmul2(esA1, eAhi), __hmul2(esB1, eBhi));
            unsigned afr[4];
            afr[0] = (*(unsigned*)&p0lo) & lut_s[(aw0 >> b0) & 3u];
            afr[1] = (*(unsigned*)&p1lo) & lut_s[(aw1 >> b0) & 3u];
            afr[2] = (*(unsigned*)&p0hi) & lut_s[(aw0 >> b2) & 3u];
            afr[3] = (*(unsigned*)&p1hi) & lut_s[(aw1 >> b2) & 3u];
            if (w < 4) mma16816(accd, afr, ONES2, ONES2);   // row sums (denom)
            #pragma unroll
            for (int nj = 0; nj < N16; nj++) {
                unsigned bfr[4];
                ldsm4t(bfr, hbc +
                       ((k16 * 16 + (lane & 15)) * HSTR +
                        wn + nj * 16 + (lane >> 4) * 8) * 2);
                mma16816(acc[2 * nj],     afr, bfr[0], bfr[1]);
                mma16816(acc[2 * nj + 1], afr, bfr[2], bfr[3]);
            }
        }
        __syncthreads();                     // done with buf cur before reuse
    }
#undef STG_H
#undef STG_EA

    // denominators: accd[0]=row wm+g, accd[2]=row wm+g+8 (all tig identical)
    if (w < 4 && tig == 0) {
        dpart_s[wm + g]     = accd[0];
        dpart_s[wm + g + 8] = accd[2];
    }
    __syncthreads();
    if (tid < BM) {
        if (LAYER == 1) inv_s[tid] = 1.f / dpart_s[tid];
        else            PDEN[js * GN + i0 + tid] = dpart_s[tid];
    }
    __syncthreads();

    if (LAYER == 1) {
        int rr0 = wm + g;
        float inv0 = inv_s[rr0], inv1 = inv_s[rr0 + 8];
        #pragma unroll
        for (int f = 0; f < 2 * N16; f++) {
            int col = wn + f * 8 + tig * 2;
            float v0 = acc[f][0] * inv0;
            float v1 = acc[f][1] * inv0;
            float v2 = acc[f][2] * inv1;
            float v3 = acc[f][3] * inv1;
            v0 = (v0 > 0.f) ? v0 : expm1f(v0);
            v1 = (v1 > 0.f) ? v1 : expm1f(v1);
            v2 = (v2 > 0.f) ? v2 : expm1f(v2);
            v3 = (v3 > 0.f) ? v3 : expm1f(v3);
            size_t o0 = (size_t)(i0 + rr0) * (NH * FH) + h * FH + col;
            size_t o1 = (size_t)(i0 + rr0 + 8) * (NH * FH) + h * FH + col;
            *(__half2*)&X2H[o0] = __floats2half2_rn(v0, v1);
            *(__half2*)&X2H[o1] = __floats2half2_rn(v2, v3);
        }
    } else {
        int rr0 = wm + g;
        #pragma unroll
        for (int f = 0; f < 2 * N16; f++) {
            int col = wn + f * 8 + tig * 2;
            float* o0 = PNUM + (size_t)js * GN * FOUT + (size_t)(i0 + rr0) * FOUT + col;
            float* o1 = PNUM + (size_t)js * GN * FOUT + (size_t)(i0 + rr0 + 8) * FOUT + col;
            *(float2*)o0 = make_float2(acc[f][0], acc[f][1]);
            *(float2*)o1 = make_float2(acc[f][2], acc[f][3]);
        }
    }
}

// ---------------- combine: sum partials, normalize, ELU, log_softmax --------
__global__ void combine_kernel(float* __restrict__ out) {
    int gw   = (blockIdx.x * blockDim.x + threadIdx.x) >> 5;   // row
    int lane = threadIdx.x & 31;
    float den = 0.f;
    #pragma unroll
    for (int js = 0; js < 4; js++) den += PDEN[js * GN + gw];
    float inv = 1.f / den;
    float v0 = 0.f, v1 = 0.f;
    #pragma unroll
    for (int js = 0; js < 4; js++) {
        const float* p = PNUM + (size_t)js * GN * FOUT + (size_t)gw * FOUT;
        v0 += p[lane];
        v1 += p[lane + 32];
    }
    v0 *= inv; v1 *= inv;
    v0 = (v0 > 0.f) ? v0 : expm1f(v0);
    v1 = (v1 > 0.f) ? v1 : expm1f(v1);
    float m = fmaxf(v0, v1);
    #pragma unroll
    for (int o = 16; o; o >>= 1) m = fmaxf(m, __shfl_xor_sync(0xffffffffu, m, o));
    float s = __expf(v0 - m) + __expf(v1 - m);
    #pragma unroll
    for (int o = 16; o; o >>= 1) s += __shfl_xor_sync(0xffffffffu, s, o);
    float lse = m + logf(s);
    out[(size_t)gw * FOUT + lane]      = v0 - lse;
    out[(size_t)gw * FOUT + lane + 32] = v1 - lse;
}

// ---------------- launch ----------------------------------------------------
extern "C" void kernel_launch(void* const* d_in, const int* in_sizes, int n_in,
                              void* d_out, int out_size) {
    const float* features = (const float*)d_in[0];
    const int*   adj      = (const int*)d_in[1];
    const float* W1  = (const float*)d_in[2];
    const float* a1s = (const float*)d_in[3];
    const float* a1d = (const float*)d_in[4];
    const float* W2  = (const float*)d_in[5];
    const float* a2s = (const float*)d_in[6];
    const float* a2d = (const float*)d_in[7];
    float* out = (float*)d_out;

    const int SM_G1 = 2 * 128 * 72 * 2 + 2 * 64 * 136 * 2;   // 71680
    const int SM_G2 = 2 * 128 * 72 * 2 + 2 * 64 * 72 * 2;    // 55296
    const int SMEM1 = 3712 + 2 * 128 * 136 * 2;              // 73344
    const int SMEM2 = 3712 + 2 * 128 * 72 * 2;               // 40576
    cudaFuncSetAttribute(hgemm_kernel<FIN, FH, 1>,
                         cudaFuncAttributeMaxDynamicSharedMemorySize, SM_G1);
    cudaFuncSetAttribute(hgemm_kernel<NH * FH, FOUT, 2>,
                         cudaFuncAttributeMaxDynamicSharedMemorySize, SM_G2);
    cudaFuncSetAttribute(attn_mma_kernel<64, FH, 1, 1>,
                         cudaFuncAttributeMaxDynamicSharedMemorySize, SMEM1);
    cudaFuncSetAttribute(attn_mma_kernel<64, FOUT, 2, 4>,
                         cudaFuncAttributeMaxDynamicSharedMemorySize, SMEM2);

    pack_adj_kernel<<<(GN * GN) / 256, 256>>>(adj, features, W1, W2);

    // layer 1
    hgemm_kernel<FIN, FH, 1><<<dim3(GN / 128, 1, NH), 256, SM_G1>>>();
    srcdst_kernel<FH, 1><<<(NH * GN) / 8, 256>>>(a1s, a1d);
    attn_mma_kernel<64, FH, 1, 1><<<dim3(GN / 64, NH, 1), 256, SMEM1>>>(nullptr);

    // layer 2
    hgemm_kernel<NH * FH, FOUT, 2><<<dim3(GN / 128, 1, 1), 256, SM_G2>>>();
    srcdst_kernel<FOUT, 2><<<GN / 8, 256>>>(a2s, a2d);
    attn_mma_kernel<64, FOUT, 2, 4><<<dim3(GN / 64, 1, 4), 256, SMEM2>>>(nullptr);
    combine_kernel<<<GN / 8, 256>>>(out);
}